// round 1
// baseline (speedup 1.0000x reference)
#include <cuda_runtime.h>
#include <math.h>

#define HWSZ 65536
#define NB 8
#define NPIX (NB * HWSZ)

__device__ float g_wmap[NPIX];    // scratch: wmap per pixel (2 MB)
__device__ float g_w[224];        // [0:64) w_score, [64:224) combined conv weights
__device__ float g_thresh[NB];    // 10th-largest score per batch

// ---------------------------------------------------------------------------
// Prep: fold w_bbx into w_width (conv operates on color*w_bbx, even channels)
// ---------------------------------------------------------------------------
__global__ void prep_weights(const float* __restrict__ w_bbx,
                             const float* __restrict__ w_width,
                             const float* __restrict__ w_score) {
    int t = threadIdx.x;
    if (t < 64) g_w[t] = w_score[t];
    if (t < 160) {
        int i = t / 5;
        g_w[64 + t] = w_bbx[2 * i] * w_width[t];
    }
}

// ---------------------------------------------------------------------------
// Kernel 1: per pixel, score (64-ch dot) + wmap (max over 32 even channels of
// 5-tap horizontal conv). Each thread handles 4 consecutive pixels (float4).
// Reads color exactly once from DRAM; halo loads are L1 hits.
// ---------------------------------------------------------------------------
__global__ void __launch_bounds__(256) k_score_wmap(
    const float* __restrict__ color, float* __restrict__ score_out) {
    __shared__ float ws[64];
    __shared__ float cwt[160];
    int t = threadIdx.x;
    if (t < 64) ws[t] = g_w[t];
    if (t < 160) cwt[t] = g_w[64 + t];
    __syncthreads();

    int p4 = (blockIdx.x * 256 + t) * 4;       // first of 4 pixels
    int b  = p4 >> 16;
    int hw = p4 & (HWSZ - 1);
    int w0 = hw & 255;
    const float* base = color + ((size_t)b * 64) * HWSZ + hw;

    float4 s = make_float4(0.f, 0.f, 0.f, 0.f);
    float m0 = -INFINITY, m1 = -INFINITY, m2 = -INFINITY, m3 = -INFINITY;
    const bool hasL = (w0 != 0), hasR = (w0 != 252);

#pragma unroll
    for (int i = 0; i < 32; i++) {
        const float* pe = base + (size_t)(2 * i) * HWSZ;
        float4 A = *(const float4*)pe;             // even channel, w0..w0+3
        float4 O = *(const float4*)(pe + HWSZ);    // odd channel
        float we = ws[2 * i], wo = ws[2 * i + 1];
        s.x = fmaf(A.x, we, fmaf(O.x, wo, s.x));
        s.y = fmaf(A.y, we, fmaf(O.y, wo, s.y));
        s.z = fmaf(A.z, we, fmaf(O.z, wo, s.z));
        s.w = fmaf(A.w, we, fmaf(O.w, wo, s.w));

        float2 L = hasL ? *(const float2*)(pe - 2) : make_float2(0.f, 0.f);
        float2 R = hasR ? *(const float2*)(pe + 4) : make_float2(0.f, 0.f);
        float c0 = cwt[5 * i], c1 = cwt[5 * i + 1], c2 = cwt[5 * i + 2],
              c3 = cwt[5 * i + 3], c4 = cwt[5 * i + 4];
        m0 = fmaxf(m0, L.x * c0 + L.y * c1 + A.x * c2 + A.y * c3 + A.z * c4);
        m1 = fmaxf(m1, L.y * c0 + A.x * c1 + A.y * c2 + A.z * c3 + A.w * c4);
        m2 = fmaxf(m2, A.x * c0 + A.y * c1 + A.z * c2 + A.w * c3 + R.x * c4);
        m3 = fmaxf(m3, A.y * c0 + A.z * c1 + A.w * c2 + R.x * c3 + R.y * c4);
    }
    *(float4*)(score_out + p4) = s;
    *(float4*)(g_wmap + p4)    = make_float4(m0, m1, m2, m3);
}

// ---------------------------------------------------------------------------
// Kernel 2: per-batch 10th-largest score. One block per batch.
// Per-thread top-10 over 64 strided elements, then 10 rounds of
// block-wide argmax-and-destroy over the 10240 candidates.
// ---------------------------------------------------------------------------
__global__ void __launch_bounds__(1024) k_topk(const float* __restrict__ score) {
    __shared__ float cand[10240];
    __shared__ float rv[1024];
    __shared__ int   ri[1024];
    int t = threadIdx.x, b = blockIdx.x;
    const float* s = score + b * HWSZ;

    float top[10];
#pragma unroll
    for (int k = 0; k < 10; k++) top[k] = -INFINITY;
    for (int j = 0; j < 64; j++) {
        float v = s[t + j * 1024];
        if (v > top[9]) {
            top[9] = v;
            for (int k = 9; k > 0; k--) {
                if (top[k] > top[k - 1]) {
                    float tmp = top[k - 1]; top[k - 1] = top[k]; top[k] = tmp;
                } else break;
            }
        }
    }
#pragma unroll
    for (int k = 0; k < 10; k++) cand[t * 10 + k] = top[k];
    __syncthreads();

    for (int r = 0; r < 10; r++) {
        float mv = -INFINITY; int mi = t * 10;
#pragma unroll
        for (int j = 0; j < 10; j++) {
            float v = cand[t * 10 + j];
            if (v > mv) { mv = v; mi = t * 10 + j; }
        }
        rv[t] = mv; ri[t] = mi;
        __syncthreads();
        for (int off = 512; off > 0; off >>= 1) {
            if (t < off && rv[t + off] > rv[t]) { rv[t] = rv[t + off]; ri[t] = ri[t + off]; }
            __syncthreads();
        }
        if (t == 0) {
            if (r == 9) g_thresh[b] = rv[0];
            cand[ri[0]] = -INFINITY;
        }
        __syncthreads();
    }
}

// ---------------------------------------------------------------------------
// Kernel 3: m + boxes. m = (score>=t10 & s>0.6) | s>0.8. Box math only
// where m (sparse: ~30 px/batch); everything else gets zeros.
// ---------------------------------------------------------------------------
__global__ void __launch_bounds__(256) k_finalize(
    const float* __restrict__ score, float* __restrict__ out_box,
    float* __restrict__ out_m) {
    int p4 = (blockIdx.x * 256 + threadIdx.x) * 4;
    int b  = p4 >> 16;
    int hw = p4 & (HWSZ - 1);
    int h = hw >> 8, w0 = hw & 255;
    float t10 = g_thresh[b];
    float4 sc = *(const float4*)(score + p4);
    float4 wm = *(const float4*)(g_wmap + p4);

    float scs[4] = {sc.x, sc.y, sc.z, sc.w};
    float wms[4] = {wm.x, wm.y, wm.z, wm.w};
    __align__(16) float res[20];
    float mv[4];

#pragma unroll
    for (int j = 0; j < 4; j++) {
        float scv = scs[j];
        float sg  = 1.0f / (1.0f + expf(-scv));
        bool m = ((scv >= t10) && (sg > 0.6f)) || (sg > 0.8f);
        float* r = res + j * 5;
        if (m) {
            float xg = (float)(w0 + j), yg = (float)h;
            float cw = expf(scv) * 10.0f;
            float ch = expf(wms[j]) * 10.0f;
            float x1 = floorf(xg - cw), x2 = ceilf(xg + cw);
            if (x1 < 0.0f || x2 > 256.0f) {
                float hv = fminf(256.0f - xg, xg);
                x1 = floorf(xg - hv); x2 = ceilf(xg + hv);
            }
            float y1 = floorf(yg - ch), y2 = ceilf(yg + ch);
            if (y1 < 0.0f || y2 > 256.0f) {
                float hh = fminf(256.0f - yg, yg);
                y1 = floorf(yg - hh); y2 = ceilf(yg + hh);
            }
            r[0] = sg; r[1] = x1; r[2] = y1; r[3] = x2; r[4] = y2;
            mv[j] = 1.0f;
        } else {
            r[0] = r[1] = r[2] = r[3] = r[4] = 0.0f;
            mv[j] = 0.0f;
        }
    }
    float* ob = out_box + (size_t)p4 * 5;   // 20 contiguous floats, 16B aligned
#pragma unroll
    for (int q = 0; q < 5; q++)
        *(float4*)(ob + q * 4) = *(const float4*)(res + q * 4);
    *(float4*)(out_m + p4) = make_float4(mv[0], mv[1], mv[2], mv[3]);
}

// ---------------------------------------------------------------------------
// Launch. Output layout: score[B*HW] | out[B*HW*5] | m[B*HW]  (all f32)
// ---------------------------------------------------------------------------
extern "C" void kernel_launch(void* const* d_in, const int* in_sizes, int n_in,
                              void* d_out, int out_size) {
    const float* color   = (const float*)d_in[1];
    const float* w_bbx   = (const float*)d_in[2];
    const float* w_width = (const float*)d_in[3];
    const float* w_score = (const float*)d_in[5];

    float* score   = (float*)d_out;
    float* out_box = score + NPIX;
    float* out_m   = out_box + (size_t)NPIX * 5;

    prep_weights<<<1, 256>>>(w_bbx, w_width, w_score);
    k_score_wmap<<<NPIX / 1024, 256>>>(color, score);
    k_topk<<<NB, 1024>>>(score);
    k_finalize<<<NPIX / 1024, 256>>>(score, out_box, out_m);
}

// round 2
// speedup vs baseline: 1.9238x; 1.9238x over previous
#include <cuda_runtime.h>
#include <math.h>

#define HWSZ 65536
#define NB 8
#define NPIX (NB * HWSZ)

__device__ float g_wmap[NPIX];     // scratch: wmap per pixel (2 MB)
__device__ float g_w[224];         // [0:64) w_score, [64:224) combined conv weights
__device__ float g_cand[512 * 10]; // per-block top-10 score candidates
__device__ float g_thresh[NB];     // 10th-largest score per batch

// ---------------------------------------------------------------------------
// Prep: fold w_bbx into w_width (conv operates on color*w_bbx, even channels)
// ---------------------------------------------------------------------------
__global__ void prep_weights(const float* __restrict__ w_bbx,
                             const float* __restrict__ w_width,
                             const float* __restrict__ w_score) {
    int t = threadIdx.x;
    if (t < 64) g_w[t] = w_score[t];
    if (t < 160) {
        int i = t / 5;
        g_w[64 + t] = w_bbx[2 * i] * w_width[t];
    }
}

// ---------------------------------------------------------------------------
// Kernel 1: per pixel, score (64-ch dot) + wmap (max over 32 even channels of
// 5-tap horizontal conv). Thread = 4 consecutive pixels. Partial unroll +
// register cap -> 3 CTAs/SM for DRAM-latency hiding.
// Tail: block-wide top-10 of the 1024 scores -> g_cand (feeds tiny reducer).
// ---------------------------------------------------------------------------
__global__ void __launch_bounds__(256, 3) k_score_wmap(
    const float* __restrict__ color, float* __restrict__ score_out) {
    __shared__ float ws[64];
    __shared__ float cwt[160];
    __shared__ float sv[1024];
    __shared__ float wvs[8];
    __shared__ int   wis[8];

    int t = threadIdx.x;
    if (t < 64) ws[t] = g_w[t];
    if (t < 160) cwt[t] = g_w[64 + t];
    __syncthreads();

    int p4 = (blockIdx.x * 256 + t) * 4;       // first of 4 pixels
    int b  = p4 >> 16;
    int hw = p4 & (HWSZ - 1);
    int w0 = hw & 255;
    const float* base = color + ((size_t)b * 64) * HWSZ + hw;

    float4 s = make_float4(0.f, 0.f, 0.f, 0.f);
    float m0 = -INFINITY, m1 = -INFINITY, m2 = -INFINITY, m3 = -INFINITY;
    const bool hasL = (w0 != 0), hasR = (w0 != 252);

#pragma unroll 4
    for (int i = 0; i < 32; i++) {
        const float* pe = base + (size_t)(2 * i) * HWSZ;
        float4 A = *(const float4*)pe;             // even channel
        float4 O = *(const float4*)(pe + HWSZ);    // odd channel
        float we = ws[2 * i], wo = ws[2 * i + 1];
        s.x = fmaf(A.x, we, fmaf(O.x, wo, s.x));
        s.y = fmaf(A.y, we, fmaf(O.y, wo, s.y));
        s.z = fmaf(A.z, we, fmaf(O.z, wo, s.z));
        s.w = fmaf(A.w, we, fmaf(O.w, wo, s.w));

        float2 L = hasL ? *(const float2*)(pe - 2) : make_float2(0.f, 0.f);
        float2 R = hasR ? *(const float2*)(pe + 4) : make_float2(0.f, 0.f);
        float c0 = cwt[5 * i], c1 = cwt[5 * i + 1], c2 = cwt[5 * i + 2],
              c3 = cwt[5 * i + 3], c4 = cwt[5 * i + 4];
        m0 = fmaxf(m0, L.x * c0 + L.y * c1 + A.x * c2 + A.y * c3 + A.z * c4);
        m1 = fmaxf(m1, L.y * c0 + A.x * c1 + A.y * c2 + A.z * c3 + A.w * c4);
        m2 = fmaxf(m2, A.x * c0 + A.y * c1 + A.z * c2 + A.w * c3 + R.x * c4);
        m3 = fmaxf(m3, A.y * c0 + A.z * c1 + A.w * c2 + R.x * c3 + R.y * c4);
    }
    *(float4*)(score_out + p4) = s;
    *(float4*)(g_wmap + p4)    = make_float4(m0, m1, m2, m3);

    // ---- block top-10 of the 1024 scores ----
    *(float4*)(sv + 4 * t) = s;
    __syncthreads();
    int lane = t & 31, wid = t >> 5;
    for (int r = 0; r < 10; r++) {
        float v = sv[t]; int vi = t;
        float v2 = sv[t + 256]; if (v2 > v) { v = v2; vi = t + 256; }
        v2 = sv[t + 512]; if (v2 > v) { v = v2; vi = t + 512; }
        v2 = sv[t + 768]; if (v2 > v) { v = v2; vi = t + 768; }
#pragma unroll
        for (int off = 16; off; off >>= 1) {
            float ov = __shfl_down_sync(0xffffffffu, v, off);
            int   oi = __shfl_down_sync(0xffffffffu, vi, off);
            if (ov > v) { v = ov; vi = oi; }
        }
        if (lane == 0) { wvs[wid] = v; wis[wid] = vi; }
        __syncthreads();
        if (t == 0) {
            float bv = wvs[0]; int bi = wis[0];
#pragma unroll
            for (int j = 1; j < 8; j++)
                if (wvs[j] > bv) { bv = wvs[j]; bi = wis[j]; }
            g_cand[blockIdx.x * 10 + r] = bv;
            sv[bi] = -INFINITY;
        }
        __syncthreads();
    }
}

// ---------------------------------------------------------------------------
// Kernel 2: exact 10th-largest per batch from 640 block candidates.
// One block per batch; 10 rounds of argmax-and-destroy.
// ---------------------------------------------------------------------------
__global__ void __launch_bounds__(256) k_thresh() {
    __shared__ float sv[640];
    __shared__ float wvs[8];
    __shared__ int   wis[8];
    int t = threadIdx.x, b = blockIdx.x;
    for (int i = t; i < 640; i += 256) sv[i] = g_cand[b * 640 + i];
    __syncthreads();
    int lane = t & 31, wid = t >> 5;
    for (int r = 0; r < 10; r++) {
        float v = -INFINITY; int vi = 0;
        for (int i = t; i < 640; i += 256) {
            float x = sv[i];
            if (x > v) { v = x; vi = i; }
        }
#pragma unroll
        for (int off = 16; off; off >>= 1) {
            float ov = __shfl_down_sync(0xffffffffu, v, off);
            int   oi = __shfl_down_sync(0xffffffffu, vi, off);
            if (ov > v) { v = ov; vi = oi; }
        }
        if (lane == 0) { wvs[wid] = v; wis[wid] = vi; }
        __syncthreads();
        if (t == 0) {
            float bv = wvs[0]; int bi = wis[0];
#pragma unroll
            for (int j = 1; j < 8; j++)
                if (wvs[j] > bv) { bv = wvs[j]; bi = wis[j]; }
            if (r == 9) g_thresh[b] = bv;
            sv[bi] = -INFINITY;
        }
        __syncthreads();
    }
}

// ---------------------------------------------------------------------------
// Kernel 3: m + boxes. m = (score>=t10 & s>0.6) | s>0.8. Box output staged
// through padded smem for fully-coalesced 32-bit stores.
// ---------------------------------------------------------------------------
__global__ void __launch_bounds__(256) k_finalize(
    const float* __restrict__ score, float* __restrict__ out_box,
    float* __restrict__ out_m) {
    __shared__ float stage[256 * 21];
    int t = threadIdx.x;
    int p4 = (blockIdx.x * 256 + t) * 4;
    int b  = p4 >> 16;
    int hw = p4 & (HWSZ - 1);
    int h = hw >> 8, w0 = hw & 255;
    float t10 = g_thresh[b];
    float4 sc = *(const float4*)(score + p4);
    float4 wm = *(const float4*)(g_wmap + p4);

    float scs[4] = {sc.x, sc.y, sc.z, sc.w};
    float wms[4] = {wm.x, wm.y, wm.z, wm.w};
    float mv[4];

#pragma unroll
    for (int j = 0; j < 4; j++) {
        float scv = scs[j];
        float sg  = 1.0f / (1.0f + expf(-scv));
        bool m = ((scv >= t10) && (sg > 0.6f)) || (sg > 0.8f);
        float* r = stage + t * 21 + j * 5;
        if (m) {
            float xg = (float)(w0 + j), yg = (float)h;
            float cw = expf(scv) * 10.0f;
            float ch = expf(wms[j]) * 10.0f;
            float x1 = floorf(xg - cw), x2 = ceilf(xg + cw);
            if (x1 < 0.0f || x2 > 256.0f) {
                float hv = fminf(256.0f - xg, xg);
                x1 = floorf(xg - hv); x2 = ceilf(xg + hv);
            }
            float y1 = floorf(yg - ch), y2 = ceilf(yg + ch);
            if (y1 < 0.0f || y2 > 256.0f) {
                float hh = fminf(256.0f - yg, yg);
                y1 = floorf(yg - hh); y2 = ceilf(yg + hh);
            }
            r[0] = sg; r[1] = x1; r[2] = y1; r[3] = x2; r[4] = y2;
            mv[j] = 1.0f;
        } else {
            r[0] = r[1] = r[2] = r[3] = r[4] = 0.0f;
            mv[j] = 0.0f;
        }
    }
    *(float4*)(out_m + p4) = make_float4(mv[0], mv[1], mv[2], mv[3]);
    __syncthreads();

    size_t obase = (size_t)blockIdx.x * 5120;
#pragma unroll 5
    for (int i = t; i < 5120; i += 256) {
        int pix = i / 20, q = i - pix * 20;
        out_box[obase + i] = stage[pix * 21 + q];
    }
}

// ---------------------------------------------------------------------------
// Launch. Output layout: score[B*HW] | out[B*HW*5] | m[B*HW]  (all f32)
// ---------------------------------------------------------------------------
extern "C" void kernel_launch(void* const* d_in, const int* in_sizes, int n_in,
                              void* d_out, int out_size) {
    const float* color   = (const float*)d_in[1];
    const float* w_bbx   = (const float*)d_in[2];
    const float* w_width = (const float*)d_in[3];
    const float* w_score = (const float*)d_in[5];

    float* score   = (float*)d_out;
    float* out_box = score + NPIX;
    float* out_m   = out_box + (size_t)NPIX * 5;

    prep_weights<<<1, 256>>>(w_bbx, w_width, w_score);
    k_score_wmap<<<NPIX / 1024, 256>>>(color, score);
    k_thresh<<<NB, 256>>>();
    k_finalize<<<NPIX / 1024, 256>>>(score, out_box, out_m);
}